// round 1
// baseline (speedup 1.0000x reference)
#include <cuda_runtime.h>

#define B_ 1000
#define T_ 512
#define L_ 25
#define E_ 64
#define H_ 8

// Scratch: precomputed layer-0 input projection (+ layer-0 bias), layout [T, B, H]
__device__ float g_xh0[(size_t)T_ * B_ * H_];

__device__ __forceinline__ float fast_tanh(float x) {
    // accurate enough (~1e-7 abs err): tanh(x) = 1 - 2/(exp(2x)+1)
    float e = __expf(2.0f * x);
    return 1.0f - __fdividef(2.0f, e + 1.0f);
}

// -------- Kernel 1: xh0[t,b,:] = emb[x[b,t]] @ W_xh0 + b_h[0] --------
__global__ void precompute_kernel(const int* __restrict__ x,
                                  const float* __restrict__ emb,
                                  const float* __restrict__ W_xh0,
                                  const float* __restrict__ b_h) {
    __shared__ float sW[E_ * H_];
    for (int i = threadIdx.x; i < E_ * H_; i += blockDim.x) sW[i] = W_xh0[i];
    __syncthreads();

    long idx = (long)blockIdx.x * blockDim.x + threadIdx.x;
    const long total = (long)B_ * T_ * H_;
    if (idx >= total) return;
    int j = (int)(idx & (H_ - 1));
    long row = idx >> 3;          // (b, t) row index
    int t = (int)(row % T_);
    int b = (int)(row / T_);
    int id = x[b * T_ + t];

    const float4* e4 = (const float4*)(emb + (long)id * E_);
    float acc = b_h[j];
#pragma unroll
    for (int k4 = 0; k4 < E_ / 4; k4++) {
        float4 v = e4[k4];
        acc += v.x * sW[(k4 * 4 + 0) * H_ + j];
        acc += v.y * sW[(k4 * 4 + 1) * H_ + j];
        acc += v.z * sW[(k4 * 4 + 2) * H_ + j];
        acc += v.w * sW[(k4 * 4 + 3) * H_ + j];
    }
    g_xh0[((long)t * B_ + b) * H_ + j] = acc;
}

// -------- Kernel 2: the recurrence. 8 threads per batch element. --------
__global__ void __launch_bounds__(64, 1) rnn_kernel(
    const float* __restrict__ h0,
    const float* __restrict__ W_xh_rest,   // [L-1, H, H]
    const float* __restrict__ W_hh,        // [L, H, H]
    const float* __restrict__ b_h,         // [L, H]
    const float* __restrict__ W_hy,        // [H, 1]
    const float* __restrict__ b_y,         // [1]
    float* __restrict__ out, int out_size) {

    __shared__ float sWx[(L_ - 1) * H_ * H_];   // 1536 f
    __shared__ float sWhh[L_ * H_ * H_];        // 1600 f
    __shared__ float sB[L_ * H_];               // 200 f
    __shared__ float sWhy[H_];
    __shared__ float sby[1];

    for (int i = threadIdx.x; i < (L_ - 1) * H_ * H_; i += blockDim.x) sWx[i] = W_xh_rest[i];
    for (int i = threadIdx.x; i < L_ * H_ * H_; i += blockDim.x) sWhh[i] = W_hh[i];
    for (int i = threadIdx.x; i < L_ * H_; i += blockDim.x) sB[i] = b_h[i];
    if (threadIdx.x < H_) sWhy[threadIdx.x] = W_hy[threadIdx.x];
    if (threadIdx.x == 0) sby[0] = b_y[0];
    __syncthreads();

    const int tid = threadIdx.x;
    const int j = tid & 7;                 // hidden unit owned by this thread
    const int lane = tid & 31;
    const int base = lane & ~7;            // first lane of this 8-lane group
    const int elem = blockIdx.x * 8 + (tid >> 3);   // batch element (grid = 125 => always < B_)

    // hidden state for all layers, in registers
    float h[L_];
#pragma unroll
    for (int i = 0; i < L_; i++) h[i] = h0[(i * B_ + elem) * H_ + j];

    // prefetch t=0 input projection
    float x0 = g_xh0[elem * H_ + j];

#pragma unroll 1
    for (int t = 0; t < T_; t++) {
        // prefetch next step (keeps LDG latency off the dependence chain)
        float x0n = (t + 1 < T_) ? g_xh0[((t + 1) * B_ + elem) * H_ + j] : 0.0f;

        // ---- layer 0: input projection precomputed (bias folded in) ----
        float a0 = x0;
        float c0 = 0.0f;
#pragma unroll
        for (int k = 0; k < 8; k++) {
            float hk = __shfl_sync(0xffffffffu, h[0], base + k);
            if (k & 1) c0 += hk * sWhh[k * H_ + j];
            else       a0 += hk * sWhh[k * H_ + j];
        }
        float o = fast_tanh(a0 + c0);
        h[0] = o;

        // ---- layers 1..24 ----
#pragma unroll
        for (int i = 1; i < L_; i++) {
            float a = sB[i * H_ + j];
            float c = 0.0f;
#pragma unroll
            for (int k = 0; k < 8; k++) {
                float ik = __shfl_sync(0xffffffffu, o, base + k);
                float hk = __shfl_sync(0xffffffffu, h[i], base + k);
                a += ik * sWx[((i - 1) * H_ + k) * H_ + j];
                c += hk * sWhh[(i * H_ + k) * H_ + j];
            }
            o = fast_tanh(a + c);
            h[i] = o;
        }
        x0 = x0n;
    }

    // ---- logits: dot(h[L-1], W_hy) + b_y, reduced across the 8-lane group ----
    float v = h[L_ - 1] * sWhy[j];
    v += __shfl_xor_sync(0xffffffffu, v, 1);
    v += __shfl_xor_sync(0xffffffffu, v, 2);
    v += __shfl_xor_sync(0xffffffffu, v, 4);
    if (j == 0 && elem < out_size) out[elem] = v + sby[0];

    // ---- h_last: [L, B, H] appended after logits ----
    if (out_size >= B_ + L_ * B_ * H_) {
#pragma unroll
        for (int i = 0; i < L_; i++)
            out[B_ + (i * B_ + elem) * H_ + j] = h[i];
    }
}

extern "C" void kernel_launch(void* const* d_in, const int* in_sizes, int n_in,
                              void* d_out, int out_size) {
    const int*   x          = (const int*)d_in[0];
    const float* h0         = (const float*)d_in[1];
    const float* emb        = (const float*)d_in[2];
    const float* W_xh0      = (const float*)d_in[3];
    const float* W_xh_rest  = (const float*)d_in[4];
    const float* W_hh       = (const float*)d_in[5];
    const float* b_h        = (const float*)d_in[6];
    const float* W_hy       = (const float*)d_in[7];
    const float* b_y        = (const float*)d_in[8];

    const long total = (long)B_ * T_ * H_;
    const int blk = 256;
    precompute_kernel<<<(int)((total + blk - 1) / blk), blk>>>(x, emb, W_xh0, b_h);

    rnn_kernel<<<B_ / 8, 64>>>(h0, W_xh_rest, W_hh, b_h, W_hy, b_y,
                               (float*)d_out, out_size);
}

// round 2
// speedup vs baseline: 3.6173x; 3.6173x over previous
#include <cuda_runtime.h>

#define B_ 1000
#define T_ 512
#define L_ 25
#define E_ 64
#define H_ 8
#define TICKS (T_ + L_ - 1)   // 536

// Scratch: layer-0 input projection (+ bias), layout [T, B, H]
__device__ float g_xh0[(size_t)T_ * B_ * H_];

__device__ __forceinline__ float fast_tanh(float x) {
    // ~1e-7 abs err: tanh(x) = 1 - 2/(exp(2x)+1)
    float e = __expf(2.0f * x);
    return 1.0f - __fdividef(2.0f, e + 1.0f);
}

// -------- Kernel 1: xh0[t,b,:] = emb[x[b,t]] @ W_xh0 + b_h[0] --------
// One thread per (b,t): reads the 256B embedding row once, produces all 8 outputs.
__global__ void precompute_kernel(const int* __restrict__ x,
                                  const float* __restrict__ emb,
                                  const float* __restrict__ W_xh0,
                                  const float* __restrict__ b_h) {
    __shared__ float sW[E_ * H_];
    __shared__ float sb[H_];
    for (int i = threadIdx.x; i < E_ * H_; i += blockDim.x) sW[i] = W_xh0[i];
    if (threadIdx.x < H_) sb[threadIdx.x] = b_h[threadIdx.x];
    __syncthreads();

    int idx = blockIdx.x * blockDim.x + threadIdx.x;
    if (idx >= B_ * T_) return;
    int b = idx % B_;          // consecutive threads -> consecutive b (coalesced store)
    int t = idx / B_;
    int id = x[b * T_ + t];

    const float4* e4 = (const float4*)(emb + (long)id * E_);
    float acc[H_];
#pragma unroll
    for (int jj = 0; jj < H_; jj++) acc[jj] = sb[jj];
#pragma unroll
    for (int k4 = 0; k4 < E_ / 4; k4++) {
        float4 v = e4[k4];
#pragma unroll
        for (int jj = 0; jj < H_; jj++) {
            acc[jj] += v.x * sW[(k4 * 4 + 0) * H_ + jj];
            acc[jj] += v.y * sW[(k4 * 4 + 1) * H_ + jj];
            acc[jj] += v.z * sW[(k4 * 4 + 2) * H_ + jj];
            acc[jj] += v.w * sW[(k4 * 4 + 3) * H_ + jj];
        }
    }
    float4* dst = (float4*)(g_xh0 + ((long)t * B_ + b) * H_);
    dst[0] = make_float4(acc[0], acc[1], acc[2], acc[3]);
    dst[1] = make_float4(acc[4], acc[5], acc[6], acc[7]);
}

// -------- Kernel 2: wavefront-pipelined recurrence --------
// Block = 1 batch element. 200 threads = 25 layers x 8 hidden units.
// Tick s: layer i processes timestep t = s - i. One __syncthreads per tick.
__global__ void __launch_bounds__(200, 7) rnn_wave_kernel(
    const float* __restrict__ h0,
    const float* __restrict__ W_xh_rest,   // [L-1, H, H]
    const float* __restrict__ W_hh,        // [L, H, H]
    const float* __restrict__ b_h,         // [L, H]
    const float* __restrict__ W_hy,        // [H, 1]
    const float* __restrict__ b_y,         // [1]
    float* __restrict__ out, int out_size) {

    __shared__ float4 sbuf[2][L_ + 1][2];  // double-buffered layer outputs, slot 0 = zeros
    __shared__ float  sx[T_ * H_];         // this element's precomputed layer-0 inputs (16KB)

    const int tid = threadIdx.x;           // 0..199
    const int i   = tid >> 3;              // layer 0..24
    const int j   = tid & 7;               // hidden unit
    const int b   = blockIdx.x;            // batch element

    // ---- per-thread weights in registers ----
    float wx[8], whh[8];
#pragma unroll
    for (int k = 0; k < 8; k++) {
        wx[k]  = (i == 0) ? 0.0f : W_xh_rest[((i - 1) * H_ + k) * H_ + j];
        whh[k] = W_hh[(i * H_ + k) * H_ + j];
    }
    const float bias = (i == 0) ? 0.0f : b_h[i * H_ + j];

    // ---- init smem state ----
    float o = h0[(i * B_ + b) * H_ + j];   // running hidden value of (layer i, unit j)
    ((float*)&sbuf[0][i + 1][0])[j] = o;
    ((float*)&sbuf[1][i + 1][0])[j] = o;
    if (tid < 8) {
        ((float*)&sbuf[0][0][0])[j] = 0.0f;
        ((float*)&sbuf[1][0][0])[j] = 0.0f;
    }
    // preload this element's whole xh0 column [T][H] into smem
    {
        const float4* src = (const float4*)g_xh0;
        float4* dst = (float4*)sx;
        // sx[t*8 + half*4] = g_xh0[(t*B + b)*8 + half*4]
        for (int q = tid; q < T_ * 2; q += 200) {
            int t = q >> 1, half = q & 1;
            dst[t * 2 + half] = src[((long)t * B_ + b) * 2 + half];
        }
    }
    __syncthreads();

#pragma unroll 1
    for (int s = 0; s < TICKS; s++) {
        const int t  = s - i;
        const int rb = (s + 1) & 1;
        const int wb = s & 1;
        if ((unsigned)t < (unsigned)T_) {
            float4 v0 = sbuf[rb][i][0];        // input from layer i-1 (this timestep)
            float4 v1 = sbuf[rb][i][1];
            float4 u0 = sbuf[rb][i + 1][0];    // own h from previous timestep
            float4 u1 = sbuf[rb][i + 1][1];

            float a0 = bias;
            if (i == 0) a0 = sx[t * H_ + j];   // precomputed x-proj (+bias) for layer 0

            a0 += v0.x * wx[0];
            float a1 = v0.y * wx[1];
            float a2 = v0.z * wx[2];
            float a3 = v0.w * wx[3];
            a0 += v1.x * wx[4];
            a1 += v1.y * wx[5];
            a2 += v1.z * wx[6];
            a3 += v1.w * wx[7];
            a0 += u0.x * whh[0];
            a1 += u0.y * whh[1];
            a2 += u0.z * whh[2];
            a3 += u0.w * whh[3];
            a0 += u1.x * whh[4];
            a1 += u1.y * whh[5];
            a2 += u1.z * whh[6];
            a3 += u1.w * whh[7];

            o = fast_tanh((a0 + a1) + (a2 + a3));
            ((float*)&sbuf[wb][i + 1][0])[j] = o;
        }
        __syncthreads();
    }

    // ---- outputs ----
    // h_last: [L, B, H] after the B logits
    if (out_size >= B_ + L_ * B_ * H_)
        out[B_ + (i * B_ + b) * H_ + j] = o;

    // logits from layer 24 (threads 192..199 = warp 6 lanes 0..7)
    if (i == L_ - 1) {
        float v = o * W_hy[j];
        v += __shfl_xor_sync(0xFFu, v, 1);
        v += __shfl_xor_sync(0xFFu, v, 2);
        v += __shfl_xor_sync(0xFFu, v, 4);
        if (j == 0 && b < out_size) out[b] = v + b_y[0];
    }
}

extern "C" void kernel_launch(void* const* d_in, const int* in_sizes, int n_in,
                              void* d_out, int out_size) {
    const int*   x          = (const int*)d_in[0];
    const float* h0         = (const float*)d_in[1];
    const float* emb        = (const float*)d_in[2];
    const float* W_xh0      = (const float*)d_in[3];
    const float* W_xh_rest  = (const float*)d_in[4];
    const float* W_hh       = (const float*)d_in[5];
    const float* b_h        = (const float*)d_in[6];
    const float* W_hy       = (const float*)d_in[7];
    const float* b_y        = (const float*)d_in[8];

    const int total = B_ * T_;
    precompute_kernel<<<(total + 255) / 256, 256>>>(x, emb, W_xh0, b_h);

    rnn_wave_kernel<<<B_, 200>>>(h0, W_xh_rest, W_hh, b_h, W_hy, b_y,
                                 (float*)d_out, out_size);
}

// round 3
// speedup vs baseline: 4.3631x; 1.2062x over previous
#include <cuda_runtime.h>

#define B_ 1000
#define T_ 512
#define L_ 25
#define E_ 64
#define H_ 8
#define EB 8                       // batch elements per block
#define TICKS (T_ + L_ - 1)        // 536

// padded smem strides (in floats)
#define ESTR 20                    // per-elem slot: 16 data floats (8 dup'd vals) + 4 pad
#define SSTR (EB * ESTR)           // per-slot: 160
#define BUFW ((L_ - 1) * SSTR)     // 24 slots per buffer: 3840 floats

// Scratch: layer-0 input projection (+ bias b_h[0]), layout [T, B, H]
__device__ float g_xh0[(size_t)T_ * B_ * H_];

typedef unsigned long long ull;

__device__ __forceinline__ void fma2(ull& d, ull a, ull b) {
    asm("fma.rn.f32x2 %0, %1, %2, %0;" : "+l"(d) : "l"(a), "l"(b));
}
__device__ __forceinline__ ull pk(float lo, float hi) {
    ull r; asm("mov.b64 %0, {%1, %2};" : "=l"(r) : "f"(lo), "f"(hi)); return r;
}
__device__ __forceinline__ float2 upk(ull p) {
    float2 r; asm("mov.b64 {%0, %1}, %2;" : "=f"(r.x), "=f"(r.y) : "l"(p)); return r;
}

__device__ __forceinline__ float fast_tanh(float x) {
    // ~1e-7 abs err: tanh(x) = 1 - 2/(exp(2x)+1)
    float e = __expf(2.0f * x);
    return 1.0f - __fdividef(2.0f, e + 1.0f);
}

// -------- Kernel 1: xh0[t,b,:] = emb[x[b,t]] @ W_xh0 + b_h[0] --------
__global__ void precompute_kernel(const int* __restrict__ x,
                                  const float* __restrict__ emb,
                                  const float* __restrict__ W_xh0,
                                  const float* __restrict__ b_h) {
    __shared__ float sW[E_ * H_];
    __shared__ float sb[H_];
    for (int i = threadIdx.x; i < E_ * H_; i += blockDim.x) sW[i] = W_xh0[i];
    if (threadIdx.x < H_) sb[threadIdx.x] = b_h[threadIdx.x];
    __syncthreads();

    int idx = blockIdx.x * blockDim.x + threadIdx.x;
    if (idx >= B_ * T_) return;
    int b = idx % B_;
    int t = idx / B_;
    int id = x[b * T_ + t];

    const float4* e4 = (const float4*)(emb + (long)id * E_);
    float acc[H_];
#pragma unroll
    for (int jj = 0; jj < H_; jj++) acc[jj] = sb[jj];
#pragma unroll
    for (int k4 = 0; k4 < E_ / 4; k4++) {
        float4 v = e4[k4];
#pragma unroll
        for (int jj = 0; jj < H_; jj++) {
            acc[jj] += v.x * sW[(k4 * 4 + 0) * H_ + jj];
            acc[jj] += v.y * sW[(k4 * 4 + 1) * H_ + jj];
            acc[jj] += v.z * sW[(k4 * 4 + 2) * H_ + jj];
            acc[jj] += v.w * sW[(k4 * 4 + 3) * H_ + jj];
        }
    }
    float4* dst = (float4*)(g_xh0 + ((long)t * B_ + b) * H_);
    dst[0] = make_float4(acc[0], acc[1], acc[2], acc[3]);
    dst[1] = make_float4(acc[4], acc[5], acc[6], acc[7]);
}

// -------- Kernel 2: wavefront recurrence, 1 thread = (layer, elem, all 8 units) --------
// Block = 25 layers x 8 elems = 200 threads. Own-layer h in registers (duplicated
// f32x2 pairs); prev-layer values read from smem stored duplicated; MACs via FFMA2.
__global__ void __launch_bounds__(200, 1) rnn_wave2_kernel(
    const float* __restrict__ h0,
    const float* __restrict__ W_xh_rest,   // [L-1, H, H]
    const float* __restrict__ W_hh,        // [L, H, H]
    const float* __restrict__ b_h,         // [L, H]
    const float* __restrict__ W_hy,        // [H, 1]
    const float* __restrict__ b_y,         // [1]
    float* __restrict__ out, int out_size) {

    extern __shared__ float smem[];
    float* sbuf = smem;                    // [2][24 slots][EB][20]
    float* sx   = smem + 2 * BUFW;         // [T][EB][8]

    const int tid = threadIdx.x;           // 0..199
    const int i   = tid >> 3;              // layer 0..24
    const int e   = tid & 7;               // elem within block
    const int b   = blockIdx.x * EB + e;   // global batch element

    // ---- pack weights into f32x2 register pairs ----
    ull wxp[32], whhp[32], bp[4];
#pragma unroll
    for (int k = 0; k < 8; k++)
#pragma unroll
        for (int p = 0; p < 4; p++) {
            float a = 0.f, c = 0.f;
            if (i > 0) {
                a = W_xh_rest[((i - 1) * H_ + k) * H_ + 2 * p];
                c = W_xh_rest[((i - 1) * H_ + k) * H_ + 2 * p + 1];
            }
            wxp[k * 4 + p] = pk(a, c);
            whhp[k * 4 + p] = pk(W_hh[(i * H_ + k) * H_ + 2 * p],
                                 W_hh[(i * H_ + k) * H_ + 2 * p + 1]);
        }
#pragma unroll
    for (int p = 0; p < 4; p++) {
        float a = (i > 0) ? b_h[i * H_ + 2 * p]     : 0.f;
        float c = (i > 0) ? b_h[i * H_ + 2 * p + 1] : 0.f;
        bp[p] = pk(a, c);
    }

    // ---- own-layer h in duplicated register pairs ----
    ull hd[8];
#pragma unroll
    for (int k = 0; k < 8; k++) {
        float h = h0[(i * B_ + b) * H_ + k];
        hd[k] = pk(h, h);
    }

    // ---- stage this block's xh0 columns into smem: sx[t][e][8] ----
    {
        const float4* src = (const float4*)g_xh0;
        float4* dst = (float4*)sx;
        for (int q = tid; q < T_ * EB * 2; q += 200) {
            int half = q & 1;
            int ee = (q >> 1) & 7;
            int t = q >> 4;
            dst[(t * EB + ee) * 2 + half] =
                src[((long)t * B_ + blockIdx.x * EB + ee) * 2 + half];
        }
    }
    __syncthreads();

#pragma unroll 2
    for (int s = 0; s < TICKS; s++) {
        const int t = s - i;
        const float* rbuf = sbuf + (((s & 1) ^ 1) * BUFW);
        float* wbuf = sbuf + ((s & 1) * BUFW);

        if ((unsigned)t < (unsigned)T_) {
            ull a0, a1, a2, a3;
            if (i == 0) {
                // accumulators init directly from precomputed x-proj (+bias)
                const ulonglong2* px = (const ulonglong2*)(sx + ((long)t * EB + e) * H_);
                ulonglong2 x0 = px[0], x1 = px[1];
                a0 = x0.x; a1 = x0.y; a2 = x1.x; a3 = x1.y;
            } else {
                a0 = bp[0]; a1 = bp[1]; a2 = bp[2]; a3 = bp[3];
                const ulonglong2* pv = (const ulonglong2*)(rbuf + ((i - 1) * EB + e) * ESTR);
                ulonglong2 v0 = pv[0], v1 = pv[1], v2 = pv[2], v3 = pv[3];
                // input MACs: v values are duplicated pairs (val,val)
                fma2(a0, v0.x, wxp[0]);  fma2(a1, v0.x, wxp[1]);  fma2(a2, v0.x, wxp[2]);  fma2(a3, v0.x, wxp[3]);
                fma2(a0, v0.y, wxp[4]);  fma2(a1, v0.y, wxp[5]);  fma2(a2, v0.y, wxp[6]);  fma2(a3, v0.y, wxp[7]);
                fma2(a0, v1.x, wxp[8]);  fma2(a1, v1.x, wxp[9]);  fma2(a2, v1.x, wxp[10]); fma2(a3, v1.x, wxp[11]);
                fma2(a0, v1.y, wxp[12]); fma2(a1, v1.y, wxp[13]); fma2(a2, v1.y, wxp[14]); fma2(a3, v1.y, wxp[15]);
                fma2(a0, v2.x, wxp[16]); fma2(a1, v2.x, wxp[17]); fma2(a2, v2.x, wxp[18]); fma2(a3, v2.x, wxp[19]);
                fma2(a0, v2.y, wxp[20]); fma2(a1, v2.y, wxp[21]); fma2(a2, v2.y, wxp[22]); fma2(a3, v2.y, wxp[23]);
                fma2(a0, v3.x, wxp[24]); fma2(a1, v3.x, wxp[25]); fma2(a2, v3.x, wxp[26]); fma2(a3, v3.x, wxp[27]);
                fma2(a0, v3.y, wxp[28]); fma2(a1, v3.y, wxp[29]); fma2(a2, v3.y, wxp[30]); fma2(a3, v3.y, wxp[31]);
            }
            // recurrent MACs: own h held as duplicated pairs in registers
#pragma unroll
            for (int k = 0; k < 8; k++) {
                fma2(a0, hd[k], whhp[k * 4 + 0]);
                fma2(a1, hd[k], whhp[k * 4 + 1]);
                fma2(a2, hd[k], whhp[k * 4 + 2]);
                fma2(a3, hd[k], whhp[k * 4 + 3]);
            }
            // tanh (scalar on pair halves)
            float2 f0 = upk(a0), f1 = upk(a1), f2 = upk(a2), f3 = upk(a3);
            float o0 = fast_tanh(f0.x), o1 = fast_tanh(f0.y);
            float o2 = fast_tanh(f1.x), o3 = fast_tanh(f1.y);
            float o4 = fast_tanh(f2.x), o5 = fast_tanh(f2.y);
            float o6 = fast_tanh(f3.x), o7 = fast_tanh(f3.y);
            hd[0] = pk(o0, o0); hd[1] = pk(o1, o1);
            hd[2] = pk(o2, o2); hd[3] = pk(o3, o3);
            hd[4] = pk(o4, o4); hd[5] = pk(o5, o5);
            hd[6] = pk(o6, o6); hd[7] = pk(o7, o7);

            if (i < L_ - 1) {   // publish duplicated values for layer i+1
                ulonglong2* pw = (ulonglong2*)(wbuf + (i * EB + e) * ESTR);
                pw[0] = make_ulonglong2(hd[0], hd[1]);
                pw[1] = make_ulonglong2(hd[2], hd[3]);
                pw[2] = make_ulonglong2(hd[4], hd[5]);
                pw[3] = make_ulonglong2(hd[6], hd[7]);
            }
        }
        __syncthreads();
    }

    // ---- outputs ----
    if (out_size >= B_ + L_ * B_ * H_) {
#pragma unroll
        for (int k = 0; k < 8; k++)
            out[B_ + (i * B_ + b) * H_ + k] = upk(hd[k]).x;
    }
    if (i == L_ - 1) {
        float v = b_y[0];
#pragma unroll
        for (int k = 0; k < 8; k++) v += upk(hd[k]).x * W_hy[k];
        if (b < out_size) out[b] = v;
    }
}

extern "C" void kernel_launch(void* const* d_in, const int* in_sizes, int n_in,
                              void* d_out, int out_size) {
    const int*   x          = (const int*)d_in[0];
    const float* h0         = (const float*)d_in[1];
    const float* emb        = (const float*)d_in[2];
    const float* W_xh0      = (const float*)d_in[3];
    const float* W_xh_rest  = (const float*)d_in[4];
    const float* W_hh       = (const float*)d_in[5];
    const float* b_h        = (const float*)d_in[6];
    const float* W_hy       = (const float*)d_in[7];
    const float* b_y        = (const float*)d_in[8];

    const int total = B_ * T_;
    precompute_kernel<<<(total + 255) / 256, 256>>>(x, emb, W_xh0, b_h);

    const int smem_bytes = (2 * BUFW + T_ * EB * H_) * 4;   // ~162 KB
    cudaFuncSetAttribute(rnn_wave2_kernel,
                         cudaFuncAttributeMaxDynamicSharedMemorySize, smem_bytes);
    rnn_wave2_kernel<<<B_ / EB, 200, smem_bytes>>>(h0, W_xh_rest, W_hh, b_h,
                                                   W_hy, b_y, (float*)d_out, out_size);
}

// round 5
// speedup vs baseline: 5.3566x; 1.2277x over previous
#include <cuda_runtime.h>

#define VOCAB_ 32000
#define B_ 1000
#define T_ 512
#define L_ 25
#define E_ 64
#define H_ 8
#define TICKS (T_ + L_ - 1)        // 536

// vproj[v][j] = emb[v] @ W_xh0[:,j] + b_h[0][j]   (1 MB, L2-resident)
__device__ float g_vproj[(size_t)VOCAB_ * H_];

typedef unsigned long long ull;

__device__ __forceinline__ void fma2(ull& d, ull a, ull b) {
    asm("fma.rn.f32x2 %0, %1, %2, %0;" : "+l"(d) : "l"(a), "l"(b));
}
__device__ __forceinline__ ull pk(float lo, float hi) {
    ull r; asm("mov.b64 %0, {%1, %2};" : "=l"(r) : "f"(lo), "f"(hi)); return r;
}
__device__ __forceinline__ float2 upk(ull p) {
    float2 r; asm("mov.b64 {%0, %1}, %2;" : "=f"(r.x), "=f"(r.y) : "l"(p)); return r;
}
__device__ __forceinline__ float fast_tanh(float x) {
    // ~1e-7 abs err: tanh(x) = 1 - 2/(exp(2x)+1)
    float e = __expf(2.0f * x);
    return 1.0f - __fdividef(2.0f, e + 1.0f);
}

// -------- Kernel 1: vproj = emb @ W_xh0 + b_h[0]  (one thread per vocab row) ----
__global__ void vproj_kernel(const float* __restrict__ emb,
                             const float* __restrict__ W_xh0,
                             const float* __restrict__ b_h) {
    __shared__ float sW[E_ * H_];
    __shared__ float sb[H_];
    for (int i = threadIdx.x; i < E_ * H_; i += blockDim.x) sW[i] = W_xh0[i];
    if (threadIdx.x < H_) sb[threadIdx.x] = b_h[threadIdx.x];
    __syncthreads();

    int v = blockIdx.x * blockDim.x + threadIdx.x;
    if (v >= VOCAB_) return;

    const float4* e4 = (const float4*)(emb + (long)v * E_);
    float acc[H_];
#pragma unroll
    for (int j = 0; j < H_; j++) acc[j] = sb[j];
#pragma unroll
    for (int k4 = 0; k4 < E_ / 4; k4++) {
        float4 ev = e4[k4];
#pragma unroll
        for (int j = 0; j < H_; j++) {
            acc[j] += ev.x * sW[(k4 * 4 + 0) * H_ + j];
            acc[j] += ev.y * sW[(k4 * 4 + 1) * H_ + j];
            acc[j] += ev.z * sW[(k4 * 4 + 2) * H_ + j];
            acc[j] += ev.w * sW[(k4 * 4 + 3) * H_ + j];
        }
    }
    float4* dst = (float4*)(g_vproj + (long)v * H_);
    dst[0] = make_float4(acc[0], acc[1], acc[2], acc[3]);
    dst[1] = make_float4(acc[4], acc[5], acc[6], acc[7]);
}

// -------- Kernel 2: warp-per-element wavefront, shuffle-only exchange --------
// lane l = layer l (l<25); lanes 25..31 compute zeros. No __syncthreads in loop.
// Lane l's state commits only inside its valid window t = s - l in [0, T).
__global__ void __launch_bounds__(256, 1) rnn_warp_kernel(
    const int*   __restrict__ x,           // [B, T]
    const float* __restrict__ h0,          // [L, B, H]
    const float* __restrict__ W_xh_rest,   // [L-1, H, H]
    const float* __restrict__ W_hh,        // [L, H, H]
    const float* __restrict__ b_h,         // [L, H]
    const float* __restrict__ W_hy,        // [H, 1]
    const float* __restrict__ b_y,         // [1]
    float* __restrict__ out, int out_size) {

    const int lane = threadIdx.x & 31;
    const int b    = blockIdx.x * 8 + (threadIdx.x >> 5);   // elem (grid=125 -> b<1000)
    const bool act   = (lane < L_);
    const bool hasWx = (lane >= 1) && act;

    // ---- weights in registers (f32x2 pairs); idle/invalid lanes get zeros ----
    ull wxp[32], whhp[32], bp[4];
#pragma unroll
    for (int k = 0; k < 8; k++)
#pragma unroll
        for (int p = 0; p < 4; p++) {
            float a = 0.f, c = 0.f;
            if (hasWx) {
                a = W_xh_rest[((lane - 1) * H_ + k) * H_ + 2 * p];
                c = W_xh_rest[((lane - 1) * H_ + k) * H_ + 2 * p + 1];
            }
            wxp[k * 4 + p] = pk(a, c);
            float d = 0.f, f = 0.f;
            if (act) {
                d = W_hh[(lane * H_ + k) * H_ + 2 * p];
                f = W_hh[(lane * H_ + k) * H_ + 2 * p + 1];
            }
            whhp[k * 4 + p] = pk(d, f);
        }
#pragma unroll
    for (int p = 0; p < 4; p++) {
        float a = hasWx ? b_h[lane * H_ + 2 * p]     : 0.f;
        float c = hasWx ? b_h[lane * H_ + 2 * p + 1] : 0.f;
        bp[p] = pk(a, c);
    }

    // ---- own-layer hidden state: scalars (shfl sources) + dup'd pairs ----
    float os[8];
    ull hd[8];
#pragma unroll
    for (int k = 0; k < 8; k++) {
        os[k] = act ? h0[(lane * B_ + b) * H_ + k] : 0.f;
        hd[k] = pk(os[k], os[k]);
    }

    // ---- x-row prefetch pipeline (uniform across warp: same addresses) ----
    const int* xb = x + (long)b * T_;
    const ulonglong2* vp = (const ulonglong2*)g_vproj;   // 32B rows = 2 x ulonglong2
    int id0 = xb[0];
    int id1 = xb[1];
    ulonglong2 xrA = vp[(long)id0 * 2 + 0], xrB = vp[(long)id0 * 2 + 1];  // row(t=0)
    ulonglong2 xnA = vp[(long)id1 * 2 + 0], xnB = vp[(long)id1 * 2 + 1];  // row(t=1)
    int idn2 = xb[2];      // id for t=2
    int idn3 = xb[3];      // id for t=3

#pragma unroll 1
    for (int s = 0; s < TICKS; s++) {
        // prefetch: row(t=s+2) and id(t=s+4)
        ulonglong2 xfA = vp[(long)idn2 * 2 + 0];
        ulonglong2 xfB = vp[(long)idn2 * 2 + 1];
        int idf = xb[(s + 4 < T_) ? (s + 4) : (T_ - 1)];

        // shuffled inputs from layer (lane-1); lane 0's result unused
        float v0 = __shfl_up_sync(0xffffffffu, os[0], 1);
        float v1 = __shfl_up_sync(0xffffffffu, os[1], 1);
        float v2 = __shfl_up_sync(0xffffffffu, os[2], 1);
        float v3 = __shfl_up_sync(0xffffffffu, os[3], 1);
        float v4 = __shfl_up_sync(0xffffffffu, os[4], 1);
        float v5 = __shfl_up_sync(0xffffffffu, os[5], 1);
        float v6 = __shfl_up_sync(0xffffffffu, os[6], 1);
        float v7 = __shfl_up_sync(0xffffffffu, os[7], 1);

        // accumulators: lane 0 starts from x-projection (bias folded), others from bias
        ull a0 = (lane == 0) ? xrA.x : bp[0];
        ull a1 = (lane == 0) ? xrA.y : bp[1];
        ull a2 = (lane == 0) ? xrB.x : bp[2];
        ull a3 = (lane == 0) ? xrB.y : bp[3];

        // recurrent MACs first (independent of shfl results -> hides shfl latency)
#pragma unroll
        for (int k = 0; k < 8; k++) {
            fma2(a0, hd[k], whhp[k * 4 + 0]);
            fma2(a1, hd[k], whhp[k * 4 + 1]);
            fma2(a2, hd[k], whhp[k * 4 + 2]);
            fma2(a3, hd[k], whhp[k * 4 + 3]);
        }
        // input MACs (lane 0: wxp==0, adds nothing)
        ull d0 = pk(v0, v0), d1 = pk(v1, v1), d2 = pk(v2, v2), d3 = pk(v3, v3);
        ull d4 = pk(v4, v4), d5 = pk(v5, v5), d6 = pk(v6, v6), d7 = pk(v7, v7);
        fma2(a0, d0, wxp[0]);  fma2(a1, d0, wxp[1]);  fma2(a2, d0, wxp[2]);  fma2(a3, d0, wxp[3]);
        fma2(a0, d1, wxp[4]);  fma2(a1, d1, wxp[5]);  fma2(a2, d1, wxp[6]);  fma2(a3, d1, wxp[7]);
        fma2(a0, d2, wxp[8]);  fma2(a1, d2, wxp[9]);  fma2(a2, d2, wxp[10]); fma2(a3, d2, wxp[11]);
        fma2(a0, d3, wxp[12]); fma2(a1, d3, wxp[13]); fma2(a2, d3, wxp[14]); fma2(a3, d3, wxp[15]);
        fma2(a0, d4, wxp[16]); fma2(a1, d4, wxp[17]); fma2(a2, d4, wxp[18]); fma2(a3, d4, wxp[19]);
        fma2(a0, d5, wxp[20]); fma2(a1, d5, wxp[21]); fma2(a2, d5, wxp[22]); fma2(a3, d5, wxp[23]);
        fma2(a0, d6, wxp[24]); fma2(a1, d6, wxp[25]); fma2(a2, d6, wxp[26]); fma2(a3, d6, wxp[27]);
        fma2(a0, d7, wxp[28]); fma2(a1, d7, wxp[29]); fma2(a2, d7, wxp[30]); fma2(a3, d7, wxp[31]);

        // validity window: lane commits only for t = s - lane in [0, T)
        const bool valid = ((unsigned)(s - lane) < (unsigned)T_);

        // tanh + predicated commit
        float2 f0 = upk(a0), f1 = upk(a1), f2 = upk(a2), f3 = upk(a3);
        float n0 = fast_tanh(f0.x), n1 = fast_tanh(f0.y);
        float n2 = fast_tanh(f1.x), n3 = fast_tanh(f1.y);
        float n4 = fast_tanh(f2.x), n5 = fast_tanh(f2.y);
        float n6 = fast_tanh(f3.x), n7 = fast_tanh(f3.y);
        if (valid) {
            os[0] = n0; os[1] = n1; os[2] = n2; os[3] = n3;
            os[4] = n4; os[5] = n5; os[6] = n6; os[7] = n7;
#pragma unroll
            for (int k = 0; k < 8; k++) hd[k] = pk(os[k], os[k]);
        }

        // rotate prefetch pipeline
        xrA = xnA; xrB = xnB;
        xnA = xfA; xnB = xfB;
        idn2 = idn3; idn3 = idf;
    }

    // ---- outputs ----
    if (act && out_size >= B_ + L_ * B_ * H_) {
#pragma unroll
        for (int k = 0; k < 8; k++)
            out[B_ + (lane * B_ + b) * H_ + k] = os[k];
    }
    if (lane == L_ - 1) {
        float v = b_y[0];
#pragma unroll
        for (int k = 0; k < 8; k++) v += os[k] * W_hy[k];
        if (b < out_size) out[b] = v;
    }
}

extern "C" void kernel_launch(void* const* d_in, const int* in_sizes, int n_in,
                              void* d_out, int out_size) {
    const int*   x          = (const int*)d_in[0];
    const float* h0         = (const float*)d_in[1];
    const float* emb        = (const float*)d_in[2];
    const float* W_xh0      = (const float*)d_in[3];
    const float* W_xh_rest  = (const float*)d_in[4];
    const float* W_hh       = (const float*)d_in[5];
    const float* b_h        = (const float*)d_in[6];
    const float* W_hy       = (const float*)d_in[7];
    const float* b_y        = (const float*)d_in[8];

    vproj_kernel<<<(VOCAB_ + 255) / 256, 256>>>(emb, W_xh0, b_h);

    rnn_warp_kernel<<<B_ / 8, 256>>>(x, h0, W_xh_rest, W_hh, b_h, W_hy, b_y,
                                     (float*)d_out, out_size);
}